// round 6
// baseline (speedup 1.0000x reference)
#include <cuda_runtime.h>
#include <cuda_fp16.h>
#include <cstdint>

typedef __half  hf;
typedef __half2 hf2;
typedef unsigned u32;
typedef uint4 v4;

#define BATCH 8
#define HEADS 8
#define NSEQ  4096
#define DM    512
#define DH    64
#define RP    256
#define MTOT  (BATCH*NSEQ)

// ---------------- scratch (hi/lo fp16 planes) ----------------
__device__ hf    g_xh [MTOT*DM], g_xl [MTOT*DM];            // x [m][512]
__device__ hf    g_wth[4*DM*DM], g_wtl[4*DM*DM];            // w^T [c][k] (q,k,v,o)
__device__ hf    g_Eth[HEADS*RP*NSEQ], g_Etl[HEADS*RP*NSEQ];// E^T [h][r][n]
__device__ hf    g_Fth[HEADS*RP*NSEQ], g_Ftl[HEADS*RP*NSEQ];
__device__ hf    g_Qh [MTOT*DM], g_Ql [MTOT*DM];            // Q  [bh][n][64]
__device__ float g_K  [MTOT*DM], g_V [MTOT*DM];             // f32 [bh][n][64]
__device__ hf    g_Kth[MTOT*DM], g_Ktl[MTOT*DM];            // K^T [bh][64][4096]
__device__ hf    g_Vth[MTOT*DM], g_Vtl[MTOT*DM];
__device__ hf    g_KPh[64*RP*DH], g_KPl[64*RP*DH];          // KP [bh][r][64]
__device__ float g_VP [64*RP*DH];                           // f32 [bh][r][64]
__device__ hf    g_VPh[64*DH*RP], g_VPl[64*DH*RP];          // VP^T [bh][64][256]
__device__ hf    g_AOh[MTOT*DM], g_AOl[MTOT*DM];            // AO [m][512]

// ---------------- helpers ----------------
__device__ __forceinline__ void sp1(float v, hf& h, hf& l) {
    h = __float2half_rn(v);
    l = __float2half_rn(v - __half2float(h));
}
__device__ __forceinline__ void mma_h(float* c, const u32* a, u32 b0, u32 b1) {
    asm volatile(
        "mma.sync.aligned.m16n8k16.row.col.f32.f16.f16.f32 "
        "{%0,%1,%2,%3},{%4,%5,%6,%7},{%8,%9},{%0,%1,%2,%3};\n"
        : "+f"(c[0]), "+f"(c[1]), "+f"(c[2]), "+f"(c[3])
        : "r"(a[0]), "r"(a[1]), "r"(a[2]), "r"(a[3]), "r"(b0), "r"(b1));
}

// ---------------- marshal kernels ----------------
__global__ void splitk(const float* __restrict__ s, hf* __restrict__ hh,
                       hf* __restrict__ ll, int n) {
    long i = ((long)blockIdx.x * 256 + threadIdx.x) * 4;
    if (i >= n) return;
    float4 v = *(const float4*)(s + i);
    hf a, b, c, d, la, lb, lc, ld;
    sp1(v.x, a, la); sp1(v.y, b, lb); sp1(v.z, c, lc); sp1(v.w, d, ld);
    *(hf2*)(hh + i)     = __halves2half2(a, b);
    *(hf2*)(hh + i + 2) = __halves2half2(c, d);
    *(hf2*)(ll + i)     = __halves2half2(la, lb);
    *(hf2*)(ll + i + 2) = __halves2half2(lc, ld);
}

// dst[z][c][r] = split(src[z][r][c]).  block (32,8), grid (C/32, R/32, Z)
__global__ void tsplit(const float* __restrict__ src, hf* __restrict__ dh,
                       hf* __restrict__ dl, int R, int C, long sp, long dp) {
    __shared__ float t[32][33];
    const float* s = src + (long)blockIdx.z * sp;
    int r0 = blockIdx.y * 32, c0 = blockIdx.x * 32;
    int tx = threadIdx.x, ty = threadIdx.y;
    #pragma unroll
    for (int k = 0; k < 4; k++)
        t[ty + 8 * k][tx] = s[(long)(r0 + ty + 8 * k) * C + c0 + tx];
    __syncthreads();
    #pragma unroll
    for (int k = 0; k < 4; k++) {
        float v = t[tx][ty + 8 * k];
        long o = (long)blockIdx.z * dp + (long)(c0 + ty + 8 * k) * R + r0 + tx;
        hf h, l; sp1(v, h, l);
        dh[o] = h; dl[o] = l;
    }
}

// =====================================================================
// gemm128: C[m][c] = sum_k A[m][k] B[c][k], 3-term fp16, BM=BN=128 BK=32
// MODE 0: qkv (z: 0=Q split-store, 1=K f32, 2=V f32; head-split layout)
// MODE 1: outproj (A = AO, B = wo^T, +bias, f32 out)
// smem: 2 bufs x 4 planes x [128][40] halves = 81920 B
// =====================================================================
#define G128_SMEM (2*4*128*40*2)

template<int MODE>
__global__ __launch_bounds__(256) void gemm128(float* __restrict__ outp,
                                               const float* __restrict__ bias)
{
    extern __shared__ hf sh[];
    const int PL = 128 * 40;
    const int m0 = blockIdx.y * 128, n0 = blockIdx.x * 128;
    const int tid = threadIdx.x, wid = tid >> 5, lane = tid & 31;
    const int g = lane >> 2, tg = lane & 3;
    const int wm = (wid >> 1) * 32, wn = (wid & 1) * 64;

    const hf *Agh, *Agl, *Bgh, *Bgl;
    if (MODE == 0) {
        Agh = g_xh; Agl = g_xl;
        Bgh = g_wth + blockIdx.z * DM * DM; Bgl = g_wtl + blockIdx.z * DM * DM;
    } else {
        Agh = g_AOh; Agl = g_AOl;
        Bgh = g_wth + 3 * DM * DM; Bgl = g_wtl + 3 * DM * DM;
    }
    const int lr = tid >> 2, lc = (tid & 3) * 8;

    float acc[2][8][4] = {};

    #pragma unroll
    for (int l = 0; l < 2; l++) {
        int row = l * 64 + lr;
        *(v4*)&sh[0 * PL + row * 40 + lc] = *(const v4*)&Agh[(long)(m0 + row) * DM + lc];
        *(v4*)&sh[1 * PL + row * 40 + lc] = *(const v4*)&Agl[(long)(m0 + row) * DM + lc];
        *(v4*)&sh[2 * PL + row * 40 + lc] = *(const v4*)&Bgh[(long)(n0 + row) * DM + lc];
        *(v4*)&sh[3 * PL + row * 40 + lc] = *(const v4*)&Bgl[(long)(n0 + row) * DM + lc];
    }
    __syncthreads();

    for (int s = 0; s < 16; s++) {
        v4 pf[2][4];
        if (s + 1 < 16) {
            int k0 = (s + 1) * 32;
            #pragma unroll
            for (int l = 0; l < 2; l++) {
                int row = l * 64 + lr;
                pf[l][0] = *(const v4*)&Agh[(long)(m0 + row) * DM + k0 + lc];
                pf[l][1] = *(const v4*)&Agl[(long)(m0 + row) * DM + k0 + lc];
                pf[l][2] = *(const v4*)&Bgh[(long)(n0 + row) * DM + k0 + lc];
                pf[l][3] = *(const v4*)&Bgl[(long)(n0 + row) * DM + k0 + lc];
            }
        }
        const hf* Ah = sh + (s & 1) * 4 * PL;
        const hf* Al = Ah + PL;
        const hf* Bh = Al + PL;
        const hf* Bl = Bh + PL;
        #pragma unroll
        for (int ks = 0; ks < 2; ks++) {
            int kb = ks * 16;
            u32 ah[2][4], al[2][4];
            #pragma unroll
            for (int mt = 0; mt < 2; mt++) {
                int r = wm + mt * 16;
                ah[mt][0] = *(const u32*)&Ah[(r + g)     * 40 + kb + 2 * tg];
                ah[mt][1] = *(const u32*)&Ah[(r + g + 8) * 40 + kb + 2 * tg];
                ah[mt][2] = *(const u32*)&Ah[(r + g)     * 40 + kb + 2 * tg + 8];
                ah[mt][3] = *(const u32*)&Ah[(r + g + 8) * 40 + kb + 2 * tg + 8];
                al[mt][0] = *(const u32*)&Al[(r + g)     * 40 + kb + 2 * tg];
                al[mt][1] = *(const u32*)&Al[(r + g + 8) * 40 + kb + 2 * tg];
                al[mt][2] = *(const u32*)&Al[(r + g)     * 40 + kb + 2 * tg + 8];
                al[mt][3] = *(const u32*)&Al[(r + g + 8) * 40 + kb + 2 * tg + 8];
            }
            #pragma unroll
            for (int nt = 0; nt < 8; nt++) {
                int n = wn + nt * 8 + g;
                u32 bh0 = *(const u32*)&Bh[n * 40 + kb + 2 * tg];
                u32 bh1 = *(const u32*)&Bh[n * 40 + kb + 2 * tg + 8];
                u32 bl0 = *(const u32*)&Bl[n * 40 + kb + 2 * tg];
                u32 bl1 = *(const u32*)&Bl[n * 40 + kb + 2 * tg + 8];
                #pragma unroll
                for (int mt = 0; mt < 2; mt++) {
                    mma_h(acc[mt][nt], ah[mt], bh0, bh1);
                    mma_h(acc[mt][nt], ah[mt], bl0, bl1);
                    mma_h(acc[mt][nt], al[mt], bh0, bh1);
                }
            }
        }
        if (s + 1 < 16) {
            hf* nb = sh + ((s + 1) & 1) * 4 * PL;
            #pragma unroll
            for (int l = 0; l < 2; l++) {
                int row = l * 64 + lr;
                *(v4*)&nb[0 * PL + row * 40 + lc] = pf[l][0];
                *(v4*)&nb[1 * PL + row * 40 + lc] = pf[l][1];
                *(v4*)&nb[2 * PL + row * 40 + lc] = pf[l][2];
                *(v4*)&nb[3 * PL + row * 40 + lc] = pf[l][3];
            }
        }
        __syncthreads();
    }

    #pragma unroll
    for (int mt = 0; mt < 2; mt++)
    #pragma unroll
    for (int i = 0; i < 2; i++) {
        int m = m0 + wm + mt * 16 + g + i * 8;
        #pragma unroll
        for (int nt = 0; nt < 8; nt++) {
            int c = n0 + wn + nt * 8 + tg * 2;
            float v0 = acc[mt][nt][i * 2], v1 = acc[mt][nt][i * 2 + 1];
            if (MODE == 0) {
                int bb = m >> 12, ns = m & (NSEQ - 1), h = c >> 6, dh = c & 63;
                long o = ((long)(bb * HEADS + h) * NSEQ + ns) * DH + dh;
                if (blockIdx.z == 0) {
                    hf h0, l0, h1, l1; sp1(v0, h0, l0); sp1(v1, h1, l1);
                    *(hf2*)&g_Qh[o] = __halves2half2(h0, h1);
                    *(hf2*)&g_Ql[o] = __halves2half2(l0, l1);
                } else {
                    float* dst = (blockIdx.z == 1) ? g_K : g_V;
                    *(float2*)&dst[o] = make_float2(v0, v1);
                }
            } else {
                *(float2*)&outp[(long)m * DM + c] =
                    make_float2(v0 + bias[c], v1 + bias[c + 1]);
            }
        }
    }
}

// =====================================================================
// proj_gemm: per (bh, z): z=0 KP[r][d] = E^T K^T (split out),
//                         z=1 VP[r][d] = F^T V^T (f32 out, transposed later)
// BM=128(r) BN=64(d) BK=32, K=4096.  smem 61440 B.
// =====================================================================
#define PRJ_SMEM (2*(2*128*40 + 2*64*40)*2)

__global__ __launch_bounds__(256) void proj_gemm()
{
    extern __shared__ hf sh[];
    const int APL = 128 * 40, BPL = 64 * 40;
    const int BUF = 2 * APL + 2 * BPL;
    const int bh = blockIdx.y, h = bh & 7, z = blockIdx.z;
    const int r0 = blockIdx.x * 128;
    const hf* Agh = (z ? g_Fth : g_Eth) + (long)h * RP * NSEQ + (long)r0 * NSEQ;
    const hf* Agl = (z ? g_Ftl : g_Etl) + (long)h * RP * NSEQ + (long)r0 * NSEQ;
    const hf* Bgh = (z ? g_Vth : g_Kth) + (long)bh * DH * NSEQ;
    const hf* Bgl = (z ? g_Vtl : g_Ktl) + (long)bh * DH * NSEQ;

    const int tid = threadIdx.x, wid = tid >> 5, lane = tid & 31;
    const int g = lane >> 2, tg = lane & 3;
    const int wm = (wid >> 1) * 32, wn = (wid & 1) * 32;
    const int lr = tid >> 2, lc = (tid & 3) * 8;

    float acc[2][4][4] = {};

    #pragma unroll
    for (int l = 0; l < 2; l++) {
        int row = l * 64 + lr;
        *(v4*)&sh[row * 40 + lc]       = *(const v4*)&Agh[(long)row * NSEQ + lc];
        *(v4*)&sh[APL + row * 40 + lc] = *(const v4*)&Agl[(long)row * NSEQ + lc];
    }
    *(v4*)&sh[2 * APL + lr * 40 + lc]       = *(const v4*)&Bgh[(long)lr * NSEQ + lc];
    *(v4*)&sh[2 * APL + BPL + lr * 40 + lc] = *(const v4*)&Bgl[(long)lr * NSEQ + lc];
    __syncthreads();

    const int NST = NSEQ / 32;
    for (int s = 0; s < NST; s++) {
        v4 pa[2][2], pb[2];
        if (s + 1 < NST) {
            int k0 = (s + 1) * 32;
            #pragma unroll
            for (int l = 0; l < 2; l++) {
                int row = l * 64 + lr;
                pa[l][0] = *(const v4*)&Agh[(long)row * NSEQ + k0 + lc];
                pa[l][1] = *(const v4*)&Agl[(long)row * NSEQ + k0 + lc];
            }
            pb[0] = *(const v4*)&Bgh[(long)lr * NSEQ + k0 + lc];
            pb[1] = *(const v4*)&Bgl[(long)lr * NSEQ + k0 + lc];
        }
        const hf* Ah = sh + (s & 1) * BUF;
        const hf* Al = Ah + APL;
        const hf* Bh = Al + APL;
        const hf* Bl = Bh + BPL;
        #pragma unroll
        for (int ks = 0; ks < 2; ks++) {
            int kb = ks * 16;
            u32 ah[2][4], al[2][4];
            #pragma unroll
            for (int mt = 0; mt < 2; mt++) {
                int r = wm + mt * 16;
                ah[mt][0] = *(const u32*)&Ah[(r + g)     * 40 + kb + 2 * tg];
                ah[mt][1] = *(const u32*)&Ah[(r + g + 8) * 40 + kb + 2 * tg];
                ah[mt][2] = *(const u32*)&Ah[(r + g)     * 40 + kb + 2 * tg + 8];
                ah[mt][3] = *(const u32*)&Ah[(r + g + 8) * 40 + kb + 2 * tg + 8];
                al[mt][0] = *(const u32*)&Al[(r + g)     * 40 + kb + 2 * tg];
                al[mt][1] = *(const u32*)&Al[(r + g + 8) * 40 + kb + 2 * tg];
                al[mt][2] = *(const u32*)&Al[(r + g)     * 40 + kb + 2 * tg + 8];
                al[mt][3] = *(const u32*)&Al[(r + g + 8) * 40 + kb + 2 * tg + 8];
            }
            #pragma unroll
            for (int nt = 0; nt < 4; nt++) {
                int n = wn + nt * 8 + g;
                u32 bh0 = *(const u32*)&Bh[n * 40 + kb + 2 * tg];
                u32 bh1 = *(const u32*)&Bh[n * 40 + kb + 2 * tg + 8];
                u32 bl0 = *(const u32*)&Bl[n * 40 + kb + 2 * tg];
                u32 bl1 = *(const u32*)&Bl[n * 40 + kb + 2 * tg + 8];
                #pragma unroll
                for (int mt = 0; mt < 2; mt++) {
                    mma_h(acc[mt][nt], ah[mt], bh0, bh1);
                    mma_h(acc[mt][nt], ah[mt], bl0, bl1);
                    mma_h(acc[mt][nt], al[mt], bh0, bh1);
                }
            }
        }
        if (s + 1 < NST) {
            hf* nb = sh + ((s + 1) & 1) * BUF;
            #pragma unroll
            for (int l = 0; l < 2; l++) {
                int row = l * 64 + lr;
                *(v4*)&nb[row * 40 + lc]       = pa[l][0];
                *(v4*)&nb[APL + row * 40 + lc] = pa[l][1];
            }
            *(v4*)&nb[2 * APL + lr * 40 + lc]       = pb[0];
            *(v4*)&nb[2 * APL + BPL + lr * 40 + lc] = pb[1];
        }
        __syncthreads();
    }

    float* vout = g_VP + (long)bh * RP * DH;
    hf* kh = g_KPh + (long)bh * RP * DH;
    hf* kl = g_KPl + (long)bh * RP * DH;
    #pragma unroll
    for (int mt = 0; mt < 2; mt++)
    #pragma unroll
    for (int i = 0; i < 2; i++) {
        int r = r0 + wm + mt * 16 + g + i * 8;
        #pragma unroll
        for (int nt = 0; nt < 4; nt++) {
            int c = wn + nt * 8 + tg * 2;
            float v0 = acc[mt][nt][i * 2], v1 = acc[mt][nt][i * 2 + 1];
            if (z == 0) {
                hf h0, l0, h1, l1; sp1(v0, h0, l0); sp1(v1, h1, l1);
                *(hf2*)&kh[r * DH + c] = __halves2half2(h0, h1);
                *(hf2*)&kl[r * DH + c] = __halves2half2(l0, l1);
            } else {
                *(float2*)&vout[r * DH + c] = make_float2(v0, v1);
            }
        }
    }
}

// =====================================================================
// attn: grid (8, 64).  Persistent KP/VP^T in smem; 8 chunks of 64 Q rows.
// phase1 S = Q KP^T (3-term), f32 softmax, P split to smem,
// phase2 O = P VP (3-term), /rowsum, split-store AO.
// =====================================================================
#define AT_SMEM (227328 + 1024)

__global__ __launch_bounds__(256) void attn_kernel()
{
    extern __shared__ hf sh[];
    hf* Qh = sh;              // [64][72]
    hf* Ql = Qh + 4608;
    hf* Kh = Ql + 4608;       // [256][72]
    hf* Kl = Kh + 18432;
    hf* Vh = Kl + 18432;      // [64][264]
    hf* Vl = Vh + 16896;
    hf* Ph = Vl + 16896;      // [64][264]
    hf* Pl = Ph + 16896;
    float* redM = (float*)(Pl + 16896);  // [64][2]
    float* redS = redM + 128;

    const int bh = blockIdx.y;
    const int tid = threadIdx.x, wid = tid >> 5, lane = tid & 31;
    const int g = lane >> 2, tg = lane & 3;
    const int wm = (wid >> 1) * 16, wn = wid & 1;

    {
        const hf* kh = g_KPh + (long)bh * RP * DH;
        const hf* kl = g_KPl + (long)bh * RP * DH;
        #pragma unroll
        for (int l = 0; l < 8; l++) {
            int lin = l * 256 + tid, row = lin >> 3, c8 = (lin & 7) * 8;
            *(v4*)&Kh[row * 72 + c8] = *(const v4*)&kh[row * 64 + c8];
            *(v4*)&Kl[row * 72 + c8] = *(const v4*)&kl[row * 64 + c8];
        }
        const hf* vh = g_VPh + (long)bh * DH * RP;
        const hf* vl = g_VPl + (long)bh * DH * RP;
        #pragma unroll
        for (int l = 0; l < 8; l++) {
            int lin = l * 256 + tid, row = lin >> 5, c8 = (lin & 31) * 8;
            *(v4*)&Vh[row * 264 + c8] = *(const v4*)&vh[row * 256 + c8];
            *(v4*)&Vl[row * 264 + c8] = *(const v4*)&vl[row * 256 + c8];
        }
    }
    const int b = bh >> 3, hh = bh & 7;
    const float scale = 0.125f;

    for (int ci = 0; ci < 8; ci++) {
        const int n0 = blockIdx.x * 512 + ci * 64;
        __syncthreads();
        {
            const hf* qh = g_Qh + ((long)bh * NSEQ + n0) * DH;
            const hf* ql = g_Ql + ((long)bh * NSEQ + n0) * DH;
            #pragma unroll
            for (int l = 0; l < 2; l++) {
                int lin = l * 256 + tid, row = lin >> 3, c8 = (lin & 7) * 8;
                *(v4*)&Qh[row * 72 + c8] = *(const v4*)&qh[row * 64 + c8];
                *(v4*)&Ql[row * 72 + c8] = *(const v4*)&ql[row * 64 + c8];
            }
        }
        __syncthreads();

        // ---- phase 1 ----
        float acc[16][4] = {};
        #pragma unroll
        for (int ks = 0; ks < 4; ks++) {
            int kb = ks * 16;
            u32 ah[4], al[4];
            ah[0] = *(const u32*)&Qh[(wm + g)     * 72 + kb + 2 * tg];
            ah[1] = *(const u32*)&Qh[(wm + g + 8) * 72 + kb + 2 * tg];
            ah[2] = *(const u32*)&Qh[(wm + g)     * 72 + kb + 2 * tg + 8];
            ah[3] = *(const u32*)&Qh[(wm + g + 8) * 72 + kb + 2 * tg + 8];
            al[0] = *(const u32*)&Ql[(wm + g)     * 72 + kb + 2 * tg];
            al[1] = *(const u32*)&Ql[(wm + g + 8) * 72 + kb + 2 * tg];
            al[2] = *(const u32*)&Ql[(wm + g)     * 72 + kb + 2 * tg + 8];
            al[3] = *(const u32*)&Ql[(wm + g + 8) * 72 + kb + 2 * tg + 8];
            #pragma unroll
            for (int nt = 0; nt < 16; nt++) {
                int rr = wn * 128 + nt * 8 + g;
                u32 b0h = *(const u32*)&Kh[rr * 72 + kb + 2 * tg];
                u32 b1h = *(const u32*)&Kh[rr * 72 + kb + 2 * tg + 8];
                u32 b0l = *(const u32*)&Kl[rr * 72 + kb + 2 * tg];
                u32 b1l = *(const u32*)&Kl[rr * 72 + kb + 2 * tg + 8];
                mma_h(acc[nt], ah, b0h, b1h);
                mma_h(acc[nt], ah, b0l, b1l);
                mma_h(acc[nt], al, b0h, b1h);
            }
        }

        // ---- softmax ----
        const int r0 = wm + g, r1 = r0 + 8;
        float mx0 = -1e30f, mx1 = -1e30f;
        #pragma unroll
        for (int nt = 0; nt < 16; nt++) {
            mx0 = fmaxf(mx0, fmaxf(acc[nt][0], acc[nt][1]));
            mx1 = fmaxf(mx1, fmaxf(acc[nt][2], acc[nt][3]));
        }
        mx0 = fmaxf(mx0, __shfl_xor_sync(0xffffffffu, mx0, 1));
        mx0 = fmaxf(mx0, __shfl_xor_sync(0xffffffffu, mx0, 2));
        mx1 = fmaxf(mx1, __shfl_xor_sync(0xffffffffu, mx1, 1));
        mx1 = fmaxf(mx1, __shfl_xor_sync(0xffffffffu, mx1, 2));
        if (tg == 0) { redM[r0 * 2 + wn] = mx0; redM[r1 * 2 + wn] = mx1; }
        __syncthreads();
        mx0 = fmaxf(redM[r0 * 2], redM[r0 * 2 + 1]) * scale;
        mx1 = fmaxf(redM[r1 * 2], redM[r1 * 2 + 1]) * scale;

        float s0 = 0.f, s1 = 0.f;
        #pragma unroll
        for (int nt = 0; nt < 16; nt++) {
            int c = wn * 128 + nt * 8 + tg * 2;
            float e0 = __expf(acc[nt][0] * scale - mx0);
            float e1 = __expf(acc[nt][1] * scale - mx0);
            s0 += e0 + e1;
            hf p0, q0, p1, q1; sp1(e0, p0, q0); sp1(e1, p1, q1);
            *(hf2*)&Ph[r0 * 264 + c] = __halves2half2(p0, p1);
            *(hf2*)&Pl[r0 * 264 + c] = __halves2half2(q0, q1);
            float e2 = __expf(acc[nt][2] * scale - mx1);
            float e3 = __expf(acc[nt][3] * scale - mx1);
            s1 += e2 + e3;
            sp1(e2, p0, q0); sp1(e3, p1, q1);
            *(hf2*)&Ph[r1 * 264 + c] = __halves2half2(p0, p1);
            *(hf2*)&Pl[r1 * 264 + c] = __halves2half2(q0, q1);
        }
        s0 += __shfl_xor_sync(0xffffffffu, s0, 1);
        s0 += __shfl_xor_sync(0xffffffffu, s0, 2);
        s1 += __shfl_xor_sync(0xffffffffu, s1, 1);
        s1 += __shfl_xor_sync(0xffffffffu, s1, 2);
        if (tg == 0) { redS[r0 * 2 + wn] = s0; redS[r1 * 2 + wn] = s1; }
        __syncthreads();

        // ---- phase 2 ----
        float acc2[4][4] = {};
        #pragma unroll
        for (int ks = 0; ks < 16; ks++) {
            int kb = ks * 16;
            u32 ah[4], al[4];
            ah[0] = *(const u32*)&Ph[(wm + g)     * 264 + kb + 2 * tg];
            ah[1] = *(const u32*)&Ph[(wm + g + 8) * 264 + kb + 2 * tg];
            ah[2] = *(const u32*)&Ph[(wm + g)     * 264 + kb + 2 * tg + 8];
            ah[3] = *(const u32*)&Ph[(wm + g + 8) * 264 + kb + 2 * tg + 8];
            al[0] = *(const u32*)&Pl[(wm + g)     * 264 + kb + 2 * tg];
            al[1] = *(const u32*)&Pl[(wm + g + 8) * 264 + kb + 2 * tg];
            al[2] = *(const u32*)&Pl[(wm + g)     * 264 + kb + 2 * tg + 8];
            al[3] = *(const u32*)&Pl[(wm + g + 8) * 264 + kb + 2 * tg + 8];
            #pragma unroll
            for (int nt = 0; nt < 4; nt++) {
                int cc = wn * 32 + nt * 8 + g;
                u32 b0h = *(const u32*)&Vh[cc * 264 + kb + 2 * tg];
                u32 b1h = *(const u32*)&Vh[cc * 264 + kb + 2 * tg + 8];
                u32 b0l = *(const u32*)&Vl[cc * 264 + kb + 2 * tg];
                u32 b1l = *(const u32*)&Vl[cc * 264 + kb + 2 * tg + 8];
                mma_h(acc2[nt], ah, b0h, b1h);
                mma_h(acc2[nt], ah, b0l, b1l);
                mma_h(acc2[nt], al, b0h, b1h);
            }
        }

        float inv0 = __frcp_rn(redS[r0 * 2] + redS[r0 * 2 + 1]);
        float inv1 = __frcp_rn(redS[r1 * 2] + redS[r1 * 2 + 1]);
        hf* aoh = g_AOh + ((long)(b * NSEQ + n0)) * DM + hh * DH;
        hf* aol = g_AOl + ((long)(b * NSEQ + n0)) * DM + hh * DH;
        #pragma unroll
        for (int nt = 0; nt < 4; nt++) {
            int c = wn * 32 + nt * 8 + tg * 2;
            float v0 = acc2[nt][0] * inv0, v1 = acc2[nt][1] * inv0;
            float v2 = acc2[nt][2] * inv1, v3 = acc2[nt][3] * inv1;
            hf h0, l0, h1, l1;
            sp1(v0, h0, l0); sp1(v1, h1, l1);
            *(hf2*)&aoh[r0 * DM + c] = __halves2half2(h0, h1);
            *(hf2*)&aol[r0 * DM + c] = __halves2half2(l0, l1);
            sp1(v2, h0, l0); sp1(v3, h1, l1);
            *(hf2*)&aoh[r1 * DM + c] = __halves2half2(h0, h1);
            *(hf2*)&aol[r1 * DM + c] = __halves2half2(l0, l1);
        }
    }
}

// =====================================================================
extern "C" void kernel_launch(void* const* d_in, const int* in_sizes, int n_in,
                              void* d_out, int out_size)
{
    (void)in_sizes; (void)n_in; (void)out_size;
    const float* x  = (const float*)d_in[0];
    const float* wq = (const float*)d_in[1];
    const float* wk = (const float*)d_in[2];
    const float* wv = (const float*)d_in[3];
    const float* E  = (const float*)d_in[4];
    const float* F  = (const float*)d_in[5];
    const float* wo = (const float*)d_in[6];
    const float* bo = (const float*)d_in[7];
    float* out = (float*)d_out;

    cudaFuncSetAttribute(gemm128<0>, cudaFuncAttributeMaxDynamicSharedMemorySize, G128_SMEM);
    cudaFuncSetAttribute(gemm128<1>, cudaFuncAttributeMaxDynamicSharedMemorySize, G128_SMEM);
    cudaFuncSetAttribute(proj_gemm,  cudaFuncAttributeMaxDynamicSharedMemorySize, PRJ_SMEM);
    cudaFuncSetAttribute(attn_kernel, cudaFuncAttributeMaxDynamicSharedMemorySize, AT_SMEM);

    hf *p_xh, *p_xl, *p_wth, *p_wtl, *p_Eth, *p_Etl, *p_Fth, *p_Ftl;
    hf *p_Kth, *p_Ktl, *p_Vth, *p_Vtl, *p_VPh, *p_VPl;
    float *p_K, *p_V, *p_VP;
    cudaGetSymbolAddress((void**)&p_xh,  g_xh);  cudaGetSymbolAddress((void**)&p_xl,  g_xl);
    cudaGetSymbolAddress((void**)&p_wth, g_wth); cudaGetSymbolAddress((void**)&p_wtl, g_wtl);
    cudaGetSymbolAddress((void**)&p_Eth, g_Eth); cudaGetSymbolAddress((void**)&p_Etl, g_Etl);
    cudaGetSymbolAddress((void**)&p_Fth, g_Fth); cudaGetSymbolAddress((void**)&p_Ftl, g_Ftl);
    cudaGetSymbolAddress((void**)&p_Kth, g_Kth); cudaGetSymbolAddress((void**)&p_Ktl, g_Ktl);
    cudaGetSymbolAddress((void**)&p_Vth, g_Vth); cudaGetSymbolAddress((void**)&p_Vtl, g_Vtl);
    cudaGetSymbolAddress((void**)&p_VPh, g_VPh); cudaGetSymbolAddress((void**)&p_VPl, g_VPl);
    cudaGetSymbolAddress((void**)&p_K,   g_K);   cudaGetSymbolAddress((void**)&p_V,   g_V);
    cudaGetSymbolAddress((void**)&p_VP,  g_VP);

    dim3 tb(32, 8);
    // marshal inputs
    splitk<<<MTOT*DM/1024, 256>>>(x, p_xh, p_xl, MTOT*DM);
    tsplit<<<dim3(16,16,1), tb>>>(wq, p_wth,           p_wtl,           DM, DM, 0, 0);
    tsplit<<<dim3(16,16,1), tb>>>(wk, p_wth + DM*DM,   p_wtl + DM*DM,   DM, DM, 0, 0);
    tsplit<<<dim3(16,16,1), tb>>>(wv, p_wth + 2*DM*DM, p_wtl + 2*DM*DM, DM, DM, 0, 0);
    tsplit<<<dim3(16,16,1), tb>>>(wo, p_wth + 3*DM*DM, p_wtl + 3*DM*DM, DM, DM, 0, 0);
    tsplit<<<dim3(8,128,8), tb>>>(E, p_Eth, p_Etl, NSEQ, RP, (long)NSEQ*RP, (long)RP*NSEQ);
    tsplit<<<dim3(8,128,8), tb>>>(F, p_Fth, p_Ftl, NSEQ, RP, (long)NSEQ*RP, (long)RP*NSEQ);

    // QKV
    gemm128<0><<<dim3(4,256,3), 256, G128_SMEM>>>(nullptr, nullptr);

    // K, V -> transposed split
    tsplit<<<dim3(2,128,64), tb>>>(p_K, p_Kth, p_Ktl, NSEQ, DH, (long)NSEQ*DH, (long)DH*NSEQ);
    tsplit<<<dim3(2,128,64), tb>>>(p_V, p_Vth, p_Vtl, NSEQ, DH, (long)NSEQ*DH, (long)DH*NSEQ);

    // low-rank projections
    proj_gemm<<<dim3(2,64,2), 256, PRJ_SMEM>>>();

    // VP -> transposed split
    tsplit<<<dim3(2,8,64), tb>>>(p_VP, p_VPh, p_VPl, RP, DH, (long)RP*DH, (long)DH*RP);

    // attention
    attn_kernel<<<dim3(8,64), 256, AT_SMEM>>>();

    // output projection
    gemm128<1><<<dim3(4,256,1), 256, G128_SMEM>>>(out, bo);
}

// round 7
// speedup vs baseline: 1.7220x; 1.7220x over previous
#include <cuda_runtime.h>
#include <cstdint>

#define BATCH 8
#define HEADS 8
#define NSEQ  4096
#define DM    512
#define DH    64
#define RP    256

__device__ float g_Q [BATCH*HEADS*NSEQ*DH];
__device__ float g_K [BATCH*HEADS*NSEQ*DH];
__device__ float g_V [BATCH*HEADS*NSEQ*DH];
__device__ float g_KP[BATCH*HEADS*RP*DH];
__device__ float g_VP[BATCH*HEADS*RP*DH];
__device__ float g_AO[BATCH*NSEQ*DM];

// ---------------- helpers ----------------
__device__ __forceinline__ float f2tf(float f) {
    unsigned u; asm("cvt.rna.tf32.f32 %0, %1;" : "=r"(u) : "f"(f));
    return __uint_as_float(u);
}
__device__ __forceinline__ float4 cvt4(float4 v) {
    return make_float4(f2tf(v.x), f2tf(v.y), f2tf(v.z), f2tf(v.w));
}
__device__ __forceinline__ void mma_tf32(float c[4], float a0, float a1, float a2, float a3,
                                         float b0, float b1) {
    asm volatile(
        "mma.sync.aligned.m16n8k8.row.col.f32.tf32.tf32.f32 "
        "{%0,%1,%2,%3},{%4,%5,%6,%7},{%8,%9},{%0,%1,%2,%3};\n"
        : "+f"(c[0]), "+f"(c[1]), "+f"(c[2]), "+f"(c[3])
        : "r"(__float_as_uint(a0)), "r"(__float_as_uint(a1)),
          "r"(__float_as_uint(a2)), "r"(__float_as_uint(a3)),
          "r"(__float_as_uint(b0)), "r"(__float_as_uint(b1)));
}
__device__ __forceinline__ uint32_t s2u(const void* p) {
    return (uint32_t)__cvta_generic_to_shared(p);
}
__device__ __forceinline__ void cpa16(uint32_t dst, const void* src) {
    asm volatile("cp.async.cg.shared.global [%0], [%1], 16;\n" :: "r"(dst), "l"(src));
}
__device__ __forceinline__ void cpcommit() {
    asm volatile("cp.async.commit_group;\n" ::: "memory");
}
template<int N> __device__ __forceinline__ void cpwait() {
    asm volatile("cp.async.wait_group %0;\n" :: "n"(N) : "memory");
}

// =====================================================================
// Kernel 1: QKV.  BM=BN=128 BK=32, 3-stage cp.async, tf32 cvt at frag load.
// As: [m][36], Bs: [k][136].  Identical arithmetic to round-2 kernel.
// =====================================================================
#define QA (128*36)
#define QB (32*136)
#define QSTG (QA+QB)
#define QKV_SMEM (3*QSTG*4)

__global__ __launch_bounds__(256, 2) void qkv_kernel(
    const float* __restrict__ x, const float* __restrict__ wq,
    const float* __restrict__ wk, const float* __restrict__ wv)
{
    extern __shared__ float sm[];

    const float* w; float* outp;
    if (blockIdx.z == 0)      { w = wq; outp = g_Q; }
    else if (blockIdx.z == 1) { w = wk; outp = g_K; }
    else                      { w = wv; outp = g_V; }

    const int m0 = blockIdx.y * 128, n0 = blockIdx.x * 128;
    const int tid = threadIdx.x;
    const int wid = tid >> 5, lane = tid & 31, g = lane >> 2, tig = lane & 3;
    const int wm = (wid >> 1) * 32, wn = (wid & 1) * 64;

    const int arow = tid >> 3, acol = (tid & 7) * 4;
    const int brow = tid >> 5, bcol = (tid & 31) * 4;

    float acc[2][8][4] = {};

    auto load = [&](int s) {
        float* buf = sm + (s % 3) * QSTG;
        const int k0 = s * 32;
        const uint32_t ab = s2u(buf), bb = s2u(buf + QA);
        #pragma unroll
        for (int l = 0; l < 4; l++) {
            int r = l * 32 + arow;
            cpa16(ab + (r * 36 + acol) * 4, &x[(m0 + r) * DM + k0 + acol]);
        }
        #pragma unroll
        for (int l = 0; l < 4; l++) {
            int r = l * 8 + brow;
            cpa16(bb + (r * 136 + bcol) * 4, &w[(k0 + r) * DM + n0 + bcol]);
        }
        cpcommit();
    };

    load(0); load(1);
    for (int s = 0; s < 16; s++) {
        if (s + 2 < 16) { load(s + 2); cpwait<2>(); }
        else if (s + 1 < 16) { cpwait<1>(); }
        else { cpwait<0>(); }
        __syncthreads();          // stage s fully resident for all threads

        const float* A = sm + (s % 3) * QSTG;
        const float* B = A + QA;
        #pragma unroll
        for (int ks = 0; ks < 4; ks++) {
            int kb = ks * 8;
            float a[2][4];
            #pragma unroll
            for (int mt = 0; mt < 2; mt++) {
                int r = wm + mt * 16;
                a[mt][0] = f2tf(A[(r + g)     * 36 + kb + tig]);
                a[mt][1] = f2tf(A[(r + g + 8) * 36 + kb + tig]);
                a[mt][2] = f2tf(A[(r + g)     * 36 + kb + tig + 4]);
                a[mt][3] = f2tf(A[(r + g + 8) * 36 + kb + tig + 4]);
            }
            #pragma unroll
            for (int nt = 0; nt < 8; nt++) {
                float b0 = f2tf(B[(kb + tig)     * 136 + wn + nt * 8 + g]);
                float b1 = f2tf(B[(kb + tig + 4) * 136 + wn + nt * 8 + g]);
                #pragma unroll
                for (int mt = 0; mt < 2; mt++)
                    mma_tf32(acc[mt][nt], a[mt][0], a[mt][1], a[mt][2], a[mt][3], b0, b1);
            }
        }
        __syncthreads();          // all reads of buf s%3 done before it is reloaded
    }

    #pragma unroll
    for (int mt = 0; mt < 2; mt++) {
        #pragma unroll
        for (int i = 0; i < 2; i++) {
            int m = m0 + wm + mt * 16 + g + i * 8;
            int bb2 = m >> 12, ns = m & (NSEQ - 1);
            #pragma unroll
            for (int nt = 0; nt < 8; nt++) {
                int c = n0 + wn + nt * 8 + tig * 2;
                int h = c >> 6, dh = c & 63;
                *(float2*)&outp[((bb2 * HEADS + h) * NSEQ + ns) * DH + dh] =
                    make_float2(acc[mt][nt][i * 2], acc[mt][nt][i * 2 + 1]);
            }
        }
    }
}

// =====================================================================
// Kernel 2: low-rank proj.  BM=128(r) BN=64(d) BK=32, K=4096, 3-stage.
// =====================================================================
#define PA (32*136)
#define PB (32*72)
#define PSTG (PA+PB)
#define PRJ_SMEM (3*PSTG*4)

__global__ __launch_bounds__(256, 2) void proj_kernel(
    const float* __restrict__ E, const float* __restrict__ F)
{
    extern __shared__ float sm[];

    const int bh = blockIdx.y, h = bh & 7;
    const int r0 = blockIdx.x * 128;
    const float* P = (blockIdx.z == 0 ? E : F) + h * NSEQ * RP;
    const float* S = (blockIdx.z == 0 ? g_K : g_V) + bh * NSEQ * DH;
    float*       D = (blockIdx.z == 0 ? g_KP : g_VP) + bh * RP * DH;

    const int tid = threadIdx.x;
    const int wid = tid >> 5, lane = tid & 31, g = lane >> 2, tig = lane & 3;
    const int wm = (wid >> 1) * 32, wn = (wid & 1) * 32;

    const int arow = tid >> 5, acol = (tid & 31) * 4;
    const int brow = tid >> 4, bcol = (tid & 15) * 4;

    float acc[2][4][4] = {};

    auto load = [&](int s) {
        float* buf = sm + (s % 3) * PSTG;
        const int k0 = s * 32;
        const uint32_t ab = s2u(buf), bb = s2u(buf + PA);
        #pragma unroll
        for (int l = 0; l < 4; l++) {
            int r = l * 8 + arow;
            cpa16(ab + (r * 136 + acol) * 4, &P[(k0 + r) * RP + r0 + acol]);
        }
        #pragma unroll
        for (int l = 0; l < 2; l++) {
            int r = l * 16 + brow;
            cpa16(bb + (r * 72 + bcol) * 4, &S[(k0 + r) * DH + bcol]);
        }
        cpcommit();
    };

    const int NST = NSEQ / 32;  // 128
    load(0); load(1);
    for (int s = 0; s < NST; s++) {
        if (s + 2 < NST) { load(s + 2); cpwait<2>(); }
        else if (s + 1 < NST) { cpwait<1>(); }
        else { cpwait<0>(); }
        __syncthreads();

        const float* A = sm + (s % 3) * PSTG;
        const float* B = A + PA;
        #pragma unroll
        for (int ks = 0; ks < 4; ks++) {
            int kb = ks * 8;
            float a[2][4];
            #pragma unroll
            for (int mt = 0; mt < 2; mt++) {
                int r = wm + mt * 16;
                a[mt][0] = f2tf(A[(kb + tig)     * 136 + r0 * 0 + r + g]);
                a[mt][1] = f2tf(A[(kb + tig)     * 136 + r + g + 8]);
                a[mt][2] = f2tf(A[(kb + tig + 4) * 136 + r + g]);
                a[mt][3] = f2tf(A[(kb + tig + 4) * 136 + r + g + 8]);
            }
            #pragma unroll
            for (int nt = 0; nt < 4; nt++) {
                float b0 = f2tf(B[(kb + tig)     * 72 + wn + nt * 8 + g]);
                float b1 = f2tf(B[(kb + tig + 4) * 72 + wn + nt * 8 + g]);
                #pragma unroll
                for (int mt = 0; mt < 2; mt++)
                    mma_tf32(acc[mt][nt], a[mt][0], a[mt][1], a[mt][2], a[mt][3], b0, b1);
            }
        }
        __syncthreads();
    }

    #pragma unroll
    for (int mt = 0; mt < 2; mt++) {
        #pragma unroll
        for (int i = 0; i < 2; i++) {
            int r = r0 + wm + mt * 16 + g + i * 8;
            #pragma unroll
            for (int nt = 0; nt < 4; nt++) {
                int c = wn + nt * 8 + tig * 2;
                *(float2*)&D[r * DH + c] =
                    make_float2(acc[mt][nt][i * 2], acc[mt][nt][i * 2 + 1]);
            }
        }
    }
}

// =====================================================================
// Kernel 3: fused attention — round-2 arithmetic verbatim.
// grid (16, 64): 4 chunks of 64 Q rows per block (less tail waste).
// =====================================================================
#define AT_QS (64*68)
#define AT_KP (256*68)
#define AT_VP (256*72)
#define AT_PS (64*260)
#define AT_SMEM ((AT_QS + AT_KP + AT_VP + AT_PS + 256 + 64)*4)

__global__ __launch_bounds__(256) void attn_kernel()
{
    extern __shared__ float sm[];
    float* Qs   = sm;
    float* kps  = Qs + AT_QS;
    float* vps  = kps + AT_KP;
    float* Ps   = vps + AT_VP;
    float* redM = Ps + AT_PS;
    float* redS = redM + 128;

    const int bh = blockIdx.y;
    const float* kp = g_KP + bh * RP * DH;
    const float* vp = g_VP + bh * RP * DH;

    const int tid = threadIdx.x;
    const int wid = tid >> 5, lane = tid & 31, g = lane >> 2, tig = lane & 3;
    const int wm = (wid >> 1) * 16, wn = wid & 1;

    #pragma unroll
    for (int l = 0; l < 16; l++) {
        int idx = l * 256 + tid;
        int r = idx >> 4, c = (idx & 15) * 4;
        *(float4*)&kps[r * 68 + c] = cvt4(*(const float4*)&kp[r * DH + c]);
        *(float4*)&vps[r * 72 + c] = cvt4(*(const float4*)&vp[r * DH + c]);
    }

    const int b = bh >> 3, h = bh & 7;
    const float scale = 0.125f;

    for (int ci = 0; ci < 4; ci++) {
        const int n0 = blockIdx.x * 256 + ci * 64;
        const float* Qg = g_Q + (bh * NSEQ + n0) * DH;

        __syncthreads();
        #pragma unroll
        for (int l = 0; l < 4; l++) {
            int idx = l * 256 + tid;
            int r = idx >> 4, c = (idx & 15) * 4;
            *(float4*)&Qs[r * 68 + c] = cvt4(*(const float4*)&Qg[r * DH + c]);
        }
        __syncthreads();

        float acc[16][4] = {};
        #pragma unroll
        for (int ks = 0; ks < 8; ks++) {
            int kb = ks * 8;
            float a0 = Qs[(wm + g)     * 68 + kb + tig];
            float a1 = Qs[(wm + g + 8) * 68 + kb + tig];
            float a2 = Qs[(wm + g)     * 68 + kb + tig + 4];
            float a3 = Qs[(wm + g + 8) * 68 + kb + tig + 4];
            #pragma unroll
            for (int nt = 0; nt < 16; nt++) {
                int rr = wn * 128 + nt * 8 + g;
                float b0 = kps[rr * 68 + kb + tig];
                float b1 = kps[rr * 68 + kb + tig + 4];
                mma_tf32(acc[nt], a0, a1, a2, a3, b0, b1);
            }
        }

        const int r0 = wm + g, r1 = r0 + 8;
        float mx0 = -1e30f, mx1 = -1e30f;
        #pragma unroll
        for (int nt = 0; nt < 16; nt++) {
            mx0 = fmaxf(mx0, fmaxf(acc[nt][0], acc[nt][1]));
            mx1 = fmaxf(mx1, fmaxf(acc[nt][2], acc[nt][3]));
        }
        mx0 = fmaxf(mx0, __shfl_xor_sync(0xffffffffu, mx0, 1));
        mx0 = fmaxf(mx0, __shfl_xor_sync(0xffffffffu, mx0, 2));
        mx1 = fmaxf(mx1, __shfl_xor_sync(0xffffffffu, mx1, 1));
        mx1 = fmaxf(mx1, __shfl_xor_sync(0xffffffffu, mx1, 2));
        if (tig == 0) { redM[r0 * 2 + wn] = mx0; redM[r1 * 2 + wn] = mx1; }
        __syncthreads();
        mx0 = fmaxf(redM[r0 * 2], redM[r0 * 2 + 1]) * scale;
        mx1 = fmaxf(redM[r1 * 2], redM[r1 * 2 + 1]) * scale;

        float s0 = 0.f, s1 = 0.f;
        #pragma unroll
        for (int nt = 0; nt < 16; nt++) {
            int c = wn * 128 + nt * 8 + tig * 2;
            float e0 = __expf(acc[nt][0] * scale - mx0);
            float e1 = __expf(acc[nt][1] * scale - mx0);
            s0 += e0 + e1;
            *(float2*)&Ps[r0 * 260 + c] = make_float2(f2tf(e0), f2tf(e1));
            float e2 = __expf(acc[nt][2] * scale - mx1);
            float e3 = __expf(acc[nt][3] * scale - mx1);
            s1 += e2 + e3;
            *(float2*)&Ps[r1 * 260 + c] = make_float2(f2tf(e2), f2tf(e3));
        }
        s0 += __shfl_xor_sync(0xffffffffu, s0, 1);
        s0 += __shfl_xor_sync(0xffffffffu, s0, 2);
        s1 += __shfl_xor_sync(0xffffffffu, s1, 1);
        s1 += __shfl_xor_sync(0xffffffffu, s1, 2);
        if (tig == 0) { redS[r0 * 2 + wn] = s0; redS[r1 * 2 + wn] = s1; }
        __syncthreads();

        float acc2[4][4] = {};
        #pragma unroll 8
        for (int ks = 0; ks < 32; ks++) {
            int kb = ks * 8;
            float a0 = Ps[(wm + g)     * 260 + kb + tig];
            float a1 = Ps[(wm + g + 8) * 260 + kb + tig];
            float a2 = Ps[(wm + g)     * 260 + kb + tig + 4];
            float a3 = Ps[(wm + g + 8) * 260 + kb + tig + 4];
            #pragma unroll
            for (int nt = 0; nt < 4; nt++) {
                int cc = wn * 32 + nt * 8 + g;
                float b0 = vps[(kb + tig)     * 72 + cc];
                float b1 = vps[(kb + tig + 4) * 72 + cc];
                mma_tf32(acc2[nt], a0, a1, a2, a3, b0, b1);
            }
        }

        const float inv0 = __frcp_rn(redS[r0 * 2] + redS[r0 * 2 + 1]);
        const float inv1 = __frcp_rn(redS[r1 * 2] + redS[r1 * 2 + 1]);
        float* ao = g_AO + (long)(b * NSEQ + n0) * DM + h * DH;
        #pragma unroll
        for (int nt = 0; nt < 4; nt++) {
            int c = wn * 32 + nt * 8 + tig * 2;
            *(float2*)&ao[r0 * DM + c] = make_float2(acc2[nt][0] * inv0, acc2[nt][1] * inv0);
            *(float2*)&ao[r1 * DM + c] = make_float2(acc2[nt][2] * inv1, acc2[nt][3] * inv1);
        }
    }
}

// =====================================================================
// Kernel 4: out = AO @ w_out + b_out.  Same pipeline as qkv.
// =====================================================================
__global__ __launch_bounds__(256, 2) void outproj_kernel(
    const float* __restrict__ wo, const float* __restrict__ bo,
    float* __restrict__ out)
{
    extern __shared__ float sm[];

    const int m0 = blockIdx.y * 128, n0 = blockIdx.x * 128;
    const int tid = threadIdx.x;
    const int wid = tid >> 5, lane = tid & 31, g = lane >> 2, tig = lane & 3;
    const int wm = (wid >> 1) * 32, wn = (wid & 1) * 64;

    const int arow = tid >> 3, acol = (tid & 7) * 4;
    const int brow = tid >> 5, bcol = (tid & 31) * 4;

    float acc[2][8][4] = {};

    auto load = [&](int s) {
        float* buf = sm + (s % 3) * QSTG;
        const int k0 = s * 32;
        const uint32_t ab = s2u(buf), bb = s2u(buf + QA);
        #pragma unroll
        for (int l = 0; l < 4; l++) {
            int r = l * 32 + arow;
            cpa16(ab + (r * 36 + acol) * 4, &g_AO[(m0 + r) * DM + k0 + acol]);
        }
        #pragma unroll
        for (int l = 0; l < 4; l++) {
            int r = l * 8 + brow;
            cpa16(bb + (r * 136 + bcol) * 4, &wo[(k0 + r) * DM + n0 + bcol]);
        }
        cpcommit();
    };

    load(0); load(1);
    for (int s = 0; s < 16; s++) {
        if (s + 2 < 16) { load(s + 2); cpwait<2>(); }
        else if (s + 1 < 16) { cpwait<1>(); }
        else { cpwait<0>(); }
        __syncthreads();

        const float* A = sm + (s % 3) * QSTG;
        const float* B = A + QA;
        #pragma unroll
        for (int ks = 0; ks < 4; ks++) {
            int kb = ks * 8;
            float a[2][4];
            #pragma unroll
            for (int mt = 0; mt < 2; mt++) {
                int r = wm + mt * 16;
                a[mt][0] = f2tf(A[(r + g)     * 36 + kb + tig]);
                a[mt][1] = f2tf(A[(r + g + 8) * 36 + kb + tig]);
                a[mt][2] = f2tf(A[(r + g)     * 36 + kb + tig + 4]);
                a[mt][3] = f2tf(A[(r + g + 8) * 36 + kb + tig + 4]);
            }
            #pragma unroll
            for (int nt = 0; nt < 8; nt++) {
                float b0 = f2tf(B[(kb + tig)     * 136 + wn + nt * 8 + g]);
                float b1 = f2tf(B[(kb + tig + 4) * 136 + wn + nt * 8 + g]);
                #pragma unroll
                for (int mt = 0; mt < 2; mt++)
                    mma_tf32(acc[mt][nt], a[mt][0], a[mt][1], a[mt][2], a[mt][3], b0, b1);
            }
        }
        __syncthreads();
    }

    #pragma unroll
    for (int mt = 0; mt < 2; mt++) {
        #pragma unroll
        for (int i = 0; i < 2; i++) {
            int m = m0 + wm + mt * 16 + g + i * 8;
            #pragma unroll
            for (int nt = 0; nt < 8; nt++) {
                int c = n0 + wn + nt * 8 + tig * 2;
                float2 bias = *(const float2*)&bo[c];
                *(float2*)&out[m * DM + c] =
                    make_float2(acc[mt][nt][i * 2] + bias.x, acc[mt][nt][i * 2 + 1] + bias.y);
            }
        }
    }
}

// =====================================================================
extern "C" void kernel_launch(void* const* d_in, const int* in_sizes, int n_in,
                              void* d_out, int out_size)
{
    (void)in_sizes; (void)n_in; (void)out_size;
    const float* x  = (const float*)d_in[0];
    const float* wq = (const float*)d_in[1];
    const float* wk = (const float*)d_in[2];
    const float* wv = (const float*)d_in[3];
    const float* E  = (const float*)d_in[4];
    const float* F  = (const float*)d_in[5];
    const float* wo = (const float*)d_in[6];
    const float* bo = (const float*)d_in[7];
    float* out = (float*)d_out;

    cudaFuncSetAttribute(qkv_kernel,     cudaFuncAttributeMaxDynamicSharedMemorySize, QKV_SMEM);
    cudaFuncSetAttribute(proj_kernel,    cudaFuncAttributeMaxDynamicSharedMemorySize, PRJ_SMEM);
    cudaFuncSetAttribute(attn_kernel,    cudaFuncAttributeMaxDynamicSharedMemorySize, AT_SMEM);
    cudaFuncSetAttribute(outproj_kernel, cudaFuncAttributeMaxDynamicSharedMemorySize, QKV_SMEM);

    qkv_kernel    <<<dim3(4, 256, 3), 256, QKV_SMEM>>>(x, wq, wk, wv);
    proj_kernel   <<<dim3(2, 64, 2),  256, PRJ_SMEM>>>(E, F);
    attn_kernel   <<<dim3(16, 64),    256, AT_SMEM>>>();
    outproj_kernel<<<dim3(4, 256),    256, QKV_SMEM>>>(wo, bo, out);
}